// round 5
// baseline (speedup 1.0000x reference)
#include <cuda_runtime.h>
#include <cuda_bf16.h>
#include <mma.h>
#include <math.h>
#include <cstdint>

using namespace nvcuda;

// ---------------- problem constants ----------------
#define NMAXN   409600
#define VOCAB   32000
#define XDIM    256
#define OUTC    768          // 512 interleaved (a,b) + 256 t
#define GMAXG   512
#define NCLS    104
#define SPLIT   4

// ---------------- scratch (device globals; no allocation) ----------------
__device__ __nv_bfloat16 g_emb16[(size_t)VOCAB * XDIM];   // 16 MB, L2-resident
__device__ __nv_bfloat16 g_Wc[(size_t)XDIM * OUTC];       // fused weights, k-major [k][c]
__device__ float g_alpha[NMAXN];
__device__ int   g_start[NMAXN];                          // CSR starts (edges sorted by dst)
__device__ __nv_bfloat16 g_C[(size_t)NMAXN * XDIM];       // child message, bf16
__device__ float g_T[(size_t)NMAXN * XDIM];               // t = h@Wt (no bias); later h_final
__device__ float g_gate[NMAXN];
__device__ float g_attn[NMAXN];
__device__ float g_pooledp[(size_t)GMAXG * SPLIT * XDIM];

// ---------------- cp.async helpers ----------------
__device__ __forceinline__ uint32_t smem_u32(const void* p) {
    uint32_t a;
    asm("{ .reg .u64 t; cvta.to.shared.u64 t, %1; cvt.u32.u64 %0, t; }" : "=r"(a) : "l"(p));
    return a;
}
#define CP_ASYNC16(dst_u32, src_ptr) \
    asm volatile("cp.async.cg.shared.global [%0], [%1], 16;" \
                 :: "r"(dst_u32), "l"(src_ptr) : "memory")
#define CP_COMMIT() asm volatile("cp.async.commit_group;" ::: "memory")
#define CP_WAIT0()  asm volatile("cp.async.wait_group 0;" ::: "memory")

// ---------------- prep kernels ----------------
__global__ void conv_emb_kernel(const float* __restrict__ emb, int total4) {
    int i = blockIdx.x * blockDim.x + threadIdx.x;
    if (i < total4) {
        float4 v = ((const float4*)emb)[i];
        ((__nv_bfloat162*)g_emb16)[2 * i]     = __floats2bfloat162_rn(v.x, v.y);
        ((__nv_bfloat162*)g_emb16)[2 * i + 1] = __floats2bfloat162_rn(v.z, v.w);
    }
}

// Wc[k][2j] = Wl[k][j]; Wc[k][2j+1] = Wr[k][j]-Wl[k][j]; Wc[k][512+j] = Wt[k][j]
__global__ void build_wc_kernel(const float* __restrict__ Wl,
                                const float* __restrict__ Wr,
                                const float* __restrict__ Wt) {
    int idx = blockIdx.x * blockDim.x + threadIdx.x;
    if (idx < XDIM * OUTC) {
        int k = idx / OUTC, c = idx % OUTC;
        float v;
        if (c < 2 * XDIM) {
            int j = c >> 1;
            float l = Wl[k * XDIM + j];
            v = (c & 1) ? (Wr[k * XDIM + j] - l) : l;
        } else {
            v = Wt[k * XDIM + (c - 2 * XDIM)];
        }
        g_Wc[idx] = __float2bfloat16(v);
    }
}

// fused: alpha scatter + CSR segment starts (edges sorted by dst)
__global__ void edge_prep_kernel(const int* __restrict__ edge_src,
                                 const int* __restrict__ edge_dst,
                                 const float* __restrict__ alpha, int E) {
    int e = blockIdx.x * blockDim.x + threadIdx.x;
    if (e < E) {
        g_alpha[edge_src[e]] = alpha[e];
        int d = edge_dst[e];
        if (e == 0 || edge_dst[e - 1] != d) g_start[d] = e;
    }
}

// ---------------- persistent cp.async-pipelined wmma GEMM (512 thr / 16 warps) ----------------
// [N,256] x [256,768] bf16->fp32. Tile 128x128, grid (148, 6), 512 threads.
// Warp (wm, wn): wm = wid>>2 (32-row group), wn = wid&3 (32-col group).
// y<4: (a,b) interleaved -> alpha-combine -> g_C bf16 (64 cols at y*64), staged via smem.
// y>=4: t tile -> direct wmma store to g_T (bias added later in fin).
#define BM 128
#define BN 128
#define LDA 272                                 // A row stride (elems)
#define LDB 144                                 // B row stride (elems)
#define A_BYTES (BM * LDA * 2)                  // 69632
#define B_BYTES (XDIM * LDB * 2)                // 73728
#define GEMM_SMEM (2 * A_BYTES + B_BYTES)       // 212992

__global__ void __launch_bounds__(512, 1)
gemm_kernel(const int* __restrict__ node_type, int num_mt, int Ntot) {
    extern __shared__ __align__(16) char smem[];
    __nv_bfloat16* sAbuf[2] = { (__nv_bfloat16*)smem,
                                (__nv_bfloat16*)(smem + A_BYTES) };
    __nv_bfloat16* sB = (__nv_bfloat16*)(smem + 2 * A_BYTES);
    const uint32_t sA_u32[2] = { smem_u32(smem), smem_u32(smem + A_BYTES) };

    const int tid = threadIdx.x;
    const int wid = tid >> 5;
    const int y   = blockIdx.y;
    const int n0  = y * BN;
    const int wm  = wid >> 2, wn = wid & 3;     // 4x4 warp grid: 32x32 per warp

    // ---- stage B slice (256 x 128) once ----
    #pragma unroll 2
    for (int idx = tid; idx < XDIM * 16; idx += 512) {
        int r = idx >> 4, c = idx & 15;
        ((uint4*)(sB + r * LDB))[c] = *((const uint4*)(g_Wc + (size_t)r * OUTC + n0) + c);
    }
    // ---- prologue: async-gather first A tile into buf 0 ----
    {
        const int mt0 = blockIdx.x;
        if (mt0 < num_mt) {
            const int i0 = mt0 * BM;
            #pragma unroll 2
            for (int idx = tid; idx < BM * 32; idx += 512) {
                int r = idx >> 5, c = idx & 31;
                int row = i0 + r; if (row >= Ntot) row = 0;
                int tt = __ldg(&node_type[row]);
                CP_ASYNC16(sA_u32[0] + r * (LDA * 2) + c * 16,
                           (const char*)(g_emb16 + (size_t)tt * XDIM) + c * 16);
            }
        }
        CP_COMMIT();
        CP_WAIT0();
    }
    __syncthreads();

    int buf = 0;
    for (int mt = blockIdx.x; mt < num_mt; mt += gridDim.x) {
        const int next = mt + gridDim.x;
        const int i0 = mt * BM;

        // ---- issue prefetch of next A tile into buf^1 ----
        if (next < num_mt) {
            const int i0n = next * BM;
            const uint32_t dstb = sA_u32[buf ^ 1];
            #pragma unroll 2
            for (int idx = tid; idx < BM * 32; idx += 512) {
                int r = idx >> 5, c = idx & 31;
                int row = i0n + r; if (row >= Ntot) row = 0;
                int tt = __ldg(&node_type[row]);
                CP_ASYNC16(dstb + r * (LDA * 2) + c * 16,
                           (const char*)(g_emb16 + (size_t)tt * XDIM) + c * 16);
            }
        }
        CP_COMMIT();

        // ---- compute 32x32 per warp ----
        const __nv_bfloat16* sA = sAbuf[buf];
        wmma::fragment<wmma::accumulator, 16, 16, 16, float> acc[2][2];
        #pragma unroll
        for (int mi = 0; mi < 2; ++mi)
            #pragma unroll
            for (int ni = 0; ni < 2; ++ni)
                wmma::fill_fragment(acc[mi][ni], 0.0f);

        #pragma unroll
        for (int k = 0; k < 16; ++k) {
            const int k0 = k * 16;
            wmma::fragment<wmma::matrix_a, 16, 16, 16, __nv_bfloat16, wmma::row_major> af[2];
            wmma::fragment<wmma::matrix_b, 16, 16, 16, __nv_bfloat16, wmma::row_major> bf_[2];
            #pragma unroll
            for (int mi = 0; mi < 2; ++mi)
                wmma::load_matrix_sync(af[mi], sA + (wm * 32 + mi * 16) * LDA + k0, LDA);
            #pragma unroll
            for (int ni = 0; ni < 2; ++ni)
                wmma::load_matrix_sync(bf_[ni], sB + k0 * LDB + (wn * 32 + ni * 16), LDB);
            #pragma unroll
            for (int mi = 0; mi < 2; ++mi)
                #pragma unroll
                for (int ni = 0; ni < 2; ++ni)
                    wmma::mma_sync(acc[mi][ni], af[mi], bf_[ni], acc[mi][ni]);
        }

        if (y >= 4) {
            // ---- t tile: direct store to g_T ----
            const int cb = (y - 4) * BN;
            if (i0 + BM <= Ntot) {
                #pragma unroll
                for (int mi = 0; mi < 2; ++mi)
                    #pragma unroll
                    for (int ni = 0; ni < 2; ++ni)
                        wmma::store_matrix_sync(
                            g_T + (size_t)(i0 + wm * 32 + mi * 16) * XDIM + cb + wn * 32 + ni * 16,
                            acc[mi][ni], XDIM, wmma::mem_row_major);
            } else {
                __syncthreads();
                float* sAcc = (float*)sAbuf[buf];
                #pragma unroll
                for (int mi = 0; mi < 2; ++mi)
                    #pragma unroll
                    for (int ni = 0; ni < 2; ++ni)
                        wmma::store_matrix_sync(sAcc + (wm * 32 + mi * 16) * BN + (wn * 32 + ni * 16),
                                                acc[mi][ni], BN, wmma::mem_row_major);
                __syncthreads();
                for (int idx = tid; idx < BM * 32; idx += 512) {
                    int r = idx >> 5, q = idx & 31;
                    int node = i0 + r;
                    if (node < Ntot)
                        *(float4*)(g_T + (size_t)node * XDIM + cb + 4 * q) =
                            *(float4*)&sAcc[r * BN + 4 * q];
                }
            }
        } else {
            // ---- (a,b) tile: stage fp32, alpha-combine, write bf16 ----
            __syncthreads();                       // all warps done reading sA[buf]
            float* sAcc = (float*)sAbuf[buf];
            #pragma unroll
            for (int mi = 0; mi < 2; ++mi)
                #pragma unroll
                for (int ni = 0; ni < 2; ++ni)
                    wmma::store_matrix_sync(sAcc + (wm * 32 + mi * 16) * BN + (wn * 32 + ni * 16),
                                            acc[mi][ni], BN, wmma::mem_row_major);
            __syncthreads();
            const int jb = y * 64;
            #pragma unroll 2
            for (int idx = tid; idx < BM * 32; idx += 512) {
                int r = idx >> 5, q = idx & 31;
                int node = i0 + r;
                if (node < Ntot) {
                    float a0 = sAcc[r * BN + 4 * q + 0];
                    float b0 = sAcc[r * BN + 4 * q + 1];
                    float a1 = sAcc[r * BN + 4 * q + 2];
                    float b1 = sAcc[r * BN + 4 * q + 3];
                    float al = __ldg(&g_alpha[node]);
                    __nv_bfloat162 p2 = __floats2bfloat162_rn(fmaf(al, b0, a0),
                                                              fmaf(al, b1, a1));
                    *(__nv_bfloat162*)(g_C + (size_t)node * XDIM + jb + 2 * q) = p2;
                }
            }
        }

        CP_WAIT0();            // next A tile landed
        __syncthreads();
        buf ^= 1;
    }
}

// ---------------- aggregate children + bias + relu/select + gate (warp per node) ----------------
__global__ void fin_kernel(const int* __restrict__ node_type,
                           const int* __restrict__ edge_src,
                           const int* __restrict__ child_count,
                           const float* __restrict__ emb,
                           const float* __restrict__ b_conv,
                           const float* __restrict__ gate_w,
                           const float* __restrict__ gate_b, int N) {
    const int wid = threadIdx.x >> 5, lane = threadIdx.x & 31;
    const int p = blockIdx.x * 8 + wid;
    if (p >= N) return;

    const size_t rowoff = (size_t)p * XDIM;
    const int cc = __ldg(&child_count[p]);
    float4 v0, v1;
    if (cc > 0) {
        v0 = *(const float4*)(g_T + rowoff + lane * 4);
        v1 = *(const float4*)(g_T + rowoff + 128 + lane * 4);
        float4 bb0 = *(const float4*)(b_conv + lane * 4);
        float4 bb1 = *(const float4*)(b_conv + 128 + lane * 4);
        v0.x += bb0.x; v0.y += bb0.y; v0.z += bb0.z; v0.w += bb0.w;
        v1.x += bb1.x; v1.y += bb1.y; v1.z += bb1.z; v1.w += bb1.w;
        const int st = __ldg(&g_start[p]);
        for (int k = 0; k < cc; ++k) {
            int ch = __ldg(&edge_src[st + k]);          // uniform in warp -> broadcast
            const __nv_bfloat16* crow = g_C + (size_t)ch * XDIM;
            uint2 u0 = *(const uint2*)(crow + lane * 4);
            uint2 u1 = *(const uint2*)(crow + 128 + lane * 4);
            __nv_bfloat162 c0 = *(__nv_bfloat162*)&u0.x;
            __nv_bfloat162 c1 = *(__nv_bfloat162*)&u0.y;
            __nv_bfloat162 c2 = *(__nv_bfloat162*)&u1.x;
            __nv_bfloat162 c3 = *(__nv_bfloat162*)&u1.y;
            v0.x += __bfloat162float(c0.x); v0.y += __bfloat162float(c0.y);
            v0.z += __bfloat162float(c1.x); v0.w += __bfloat162float(c1.y);
            v1.x += __bfloat162float(c2.x); v1.y += __bfloat162float(c2.y);
            v1.z += __bfloat162float(c3.x); v1.w += __bfloat162float(c3.y);
        }
        v0.x = fmaxf(v0.x, 0.f); v0.y = fmaxf(v0.y, 0.f);
        v0.z = fmaxf(v0.z, 0.f); v0.w = fmaxf(v0.w, 0.f);
        v1.x = fmaxf(v1.x, 0.f); v1.y = fmaxf(v1.y, 0.f);
        v1.z = fmaxf(v1.z, 0.f); v1.w = fmaxf(v1.w, 0.f);
    } else {
        const float* e = emb + (size_t)__ldg(&node_type[p]) * XDIM;
        v0 = *(const float4*)(e + lane * 4);
        v1 = *(const float4*)(e + 128 + lane * 4);
    }
    *(float4*)(g_T + rowoff + lane * 4) = v0;
    *(float4*)(g_T + rowoff + 128 + lane * 4) = v1;

    float4 w0 = *(const float4*)(gate_w + lane * 4);
    float4 w1 = *(const float4*)(gate_w + 128 + lane * 4);
    float gc = v0.x * w0.x + v0.y * w0.y + v0.z * w0.z + v0.w * w0.w
             + v1.x * w1.x + v1.y * w1.y + v1.z * w1.z + v1.w * w1.w;
    #pragma unroll
    for (int off = 16; off; off >>= 1) gc += __shfl_down_sync(0xffffffffu, gc, off);
    if (lane == 0) g_gate[p] = gc + __ldg(gate_b);
}

// ---------------- per-graph softmax -> attn ----------------
__global__ void stats_kernel(int per) {
    const int g = blockIdx.x, tid = threadIdx.x;
    const int base = g * per;
    __shared__ float s_red[8];
    __shared__ float s_max, s_sum;

    float m = -1e30f;
    for (int n = tid; n < per; n += 256) m = fmaxf(m, g_gate[base + n]);
    #pragma unroll
    for (int off = 16; off; off >>= 1) m = fmaxf(m, __shfl_down_sync(0xffffffffu, m, off));
    if ((tid & 31) == 0) s_red[tid >> 5] = m;
    __syncthreads();
    if (tid == 0) {
        float mm = s_red[0];
        #pragma unroll
        for (int w = 1; w < 8; ++w) mm = fmaxf(mm, s_red[w]);
        s_max = mm;
    }
    __syncthreads();
    const float mm = s_max;

    float s = 0.0f;
    for (int n = tid; n < per; n += 256) s += expf(g_gate[base + n] - mm);
    #pragma unroll
    for (int off = 16; off; off >>= 1) s += __shfl_down_sync(0xffffffffu, s, off);
    if ((tid & 31) == 0) s_red[tid >> 5] = s;
    __syncthreads();
    if (tid == 0) {
        float ss = 0.0f;
        #pragma unroll
        for (int w = 0; w < 8; ++w) ss += s_red[w];
        s_sum = ss;
    }
    __syncthreads();
    const float inv = 1.0f / s_sum;
    for (int n = tid; n < per; n += 256) g_attn[base + n] = expf(g_gate[base + n] - mm) * inv;
}

// ---------------- weighted pooling (deterministic split-4) ----------------
__global__ void pool_kernel(int per) {
    const int g = blockIdx.x, seg = blockIdx.y, tid = threadIdx.x;
    const int chunk = per / SPLIT;
    const int n0 = g * per + seg * chunk;
    const int n1 = (seg == SPLIT - 1) ? (g * per + per) : (n0 + chunk);
    float a0 = 0.f, a1 = 0.f, a2 = 0.f, a3 = 0.f;
    int n = n0;
    for (; n + 4 <= n1; n += 4) {
        a0 = fmaf(__ldg(&g_attn[n + 0]), g_T[(size_t)(n + 0) * XDIM + tid], a0);
        a1 = fmaf(__ldg(&g_attn[n + 1]), g_T[(size_t)(n + 1) * XDIM + tid], a1);
        a2 = fmaf(__ldg(&g_attn[n + 2]), g_T[(size_t)(n + 2) * XDIM + tid], a2);
        a3 = fmaf(__ldg(&g_attn[n + 3]), g_T[(size_t)(n + 3) * XDIM + tid], a3);
    }
    for (; n < n1; ++n) a0 = fmaf(__ldg(&g_attn[n]), g_T[(size_t)n * XDIM + tid], a0);
    g_pooledp[(size_t)(g * SPLIT + seg) * XDIM + tid] = (a0 + a1) + (a2 + a3);
}

// ---------------- classifier ----------------
__global__ void final_kernel(const float* __restrict__ cls_w,
                             const float* __restrict__ cls_b,
                             float* __restrict__ out) {
    const int g = blockIdx.x, tid = threadIdx.x;   // 128 threads
    __shared__ float sp[XDIM];
    for (int c = tid; c < XDIM; c += 128) {
        float s = 0.0f;
        #pragma unroll
        for (int sgm = 0; sgm < SPLIT; ++sgm)
            s += g_pooledp[(size_t)(g * SPLIT + sgm) * XDIM + c];
        sp[c] = s;
    }
    __syncthreads();
    if (tid < NCLS) {
        float acc = cls_b[tid];
        #pragma unroll 8
        for (int c = 0; c < XDIM; ++c)
            acc = fmaf(sp[c], __ldg(&cls_w[c * NCLS + tid]), acc);
        out[g * NCLS + tid] = acc;
    }
}

// ---------------- launch ----------------
extern "C" void kernel_launch(void* const* d_in, const int* in_sizes, int n_in,
                              void* d_out, int out_size) {
    const int*   node_type   = (const int*)d_in[0];
    const int*   edge_src    = (const int*)d_in[1];
    const int*   edge_dst    = (const int*)d_in[2];
    const float* alpha       = (const float*)d_in[3];
    const int*   child_count = (const int*)d_in[4];
    // d_in[5] = graph_ids (nodes contiguous per graph; unused)
    const float* emb         = (const float*)d_in[6];
    const float* W_left      = (const float*)d_in[7];
    const float* W_right     = (const float*)d_in[8];
    const float* W_top       = (const float*)d_in[9];
    const float* b_conv      = (const float*)d_in[10];
    const float* gate_w      = (const float*)d_in[11];
    const float* gate_b      = (const float*)d_in[12];
    const float* cls_w       = (const float*)d_in[13];
    const float* cls_b       = (const float*)d_in[14];
    float* out = (float*)d_out;

    const int N = in_sizes[0];
    const int E = in_sizes[1];
    const int G = out_size / NCLS;
    const int per = N / G;
    const int num_mt = (N + BM - 1) / BM;

    cudaFuncSetAttribute(gemm_kernel, cudaFuncAttributeMaxDynamicSharedMemorySize, GEMM_SMEM);

    {   // prep (3 launches so gemm lands in the profiled 4th slot)
        int total4 = (VOCAB * XDIM) / 4;
        conv_emb_kernel<<<(total4 + 255) / 256, 256>>>(emb, total4);
        build_wc_kernel<<<(XDIM * OUTC + 255) / 256, 256>>>(W_left, W_right, W_top);
        edge_prep_kernel<<<(E + 255) / 256, 256>>>(edge_src, edge_dst, alpha, E);
    }

    dim3 gg(148, 6);
    gemm_kernel<<<gg, 512, GEMM_SMEM>>>(node_type, num_mt, N);

    fin_kernel<<<(N + 7) / 8, 256>>>(node_type, edge_src, child_count,
                                     emb, b_conv, gate_w, gate_b, N);

    stats_kernel<<<G, 256>>>(per);

    dim3 pg(G, SPLIT);
    pool_kernel<<<pg, 256>>>(per);

    final_kernel<<<G, 128>>>(cls_w, cls_b, out);
}

// round 6
// speedup vs baseline: 3.3822x; 3.3822x over previous
#include <cuda_runtime.h>
#include <cuda_bf16.h>
#include <mma.h>
#include <math.h>
#include <cstdint>

using namespace nvcuda;

// ---------------- problem constants ----------------
#define NMAXN   409600
#define VOCAB   32000
#define XDIM    256
#define OUTC    768          // 512 interleaved (a,b) + 256 t
#define GMAXG   512
#define NCLS    104
#define SPLIT   4

// ---------------- scratch (device globals; no allocation) ----------------
__device__ __nv_bfloat16 g_emb16[(size_t)VOCAB * XDIM];   // 16 MB
__device__ __nv_bfloat16 g_Wc[(size_t)XDIM * OUTC];       // fused weights, k-major [k][c]
__device__ float g_Wemb[(size_t)VOCAB * OUTC];            // emb @ Wc, fp32 (98 MB, hot in L2)
__device__ float g_alpha[NMAXN];
__device__ int   g_start[NMAXN];                          // CSR starts (edges sorted by dst)
__device__ float g_T[(size_t)NMAXN * XDIM];               // h_final
__device__ float g_gate[NMAXN];
__device__ float g_attn[NMAXN];
__device__ float g_pooledp[(size_t)GMAXG * SPLIT * XDIM];

// ---------------- prep kernels ----------------
__global__ void conv_emb_kernel(const float* __restrict__ emb, int total4) {
    int i = blockIdx.x * blockDim.x + threadIdx.x;
    if (i < total4) {
        float4 v = ((const float4*)emb)[i];
        ((__nv_bfloat162*)g_emb16)[2 * i]     = __floats2bfloat162_rn(v.x, v.y);
        ((__nv_bfloat162*)g_emb16)[2 * i + 1] = __floats2bfloat162_rn(v.z, v.w);
    }
}

// Wc[k][2j] = Wl[k][j]; Wc[k][2j+1] = Wr[k][j]-Wl[k][j]; Wc[k][512+j] = Wt[k][j]
__global__ void build_wc_kernel(const float* __restrict__ Wl,
                                const float* __restrict__ Wr,
                                const float* __restrict__ Wt) {
    int idx = blockIdx.x * blockDim.x + threadIdx.x;
    if (idx < XDIM * OUTC) {
        int k = idx / OUTC, c = idx % OUTC;
        float v;
        if (c < 2 * XDIM) {
            int j = c >> 1;
            float l = Wl[k * XDIM + j];
            v = (c & 1) ? (Wr[k * XDIM + j] - l) : l;
        } else {
            v = Wt[k * XDIM + (c - 2 * XDIM)];
        }
        g_Wc[idx] = __float2bfloat16(v);
    }
}

// fused: alpha scatter + CSR segment starts (edges sorted by dst)
__global__ void edge_prep_kernel(const int* __restrict__ edge_src,
                                 const int* __restrict__ edge_dst,
                                 const float* __restrict__ alpha, int E) {
    int e = blockIdx.x * blockDim.x + threadIdx.x;
    if (e < E) {
        g_alpha[edge_src[e]] = alpha[e];
        int d = edge_dst[e];
        if (e == 0 || edge_dst[e - 1] != d) g_start[d] = e;
    }
}

// ---------------- vocab GEMM: Wemb = emb16 @ Wc  [32000,256]x[256,768] ----------------
// 12.6 GFLOP (12.8x smaller than the per-node GEMM it replaces).
// Tile 128x128, grid (250, 6), 256 threads, direct fp32 store to g_Wemb.
#define BM 128
#define BN 128
#define LDA 272
#define LDB 144
#define A_BYTES (BM * LDA * 2)                  // 69632
#define B_BYTES (XDIM * LDB * 2)                // 73728
#define GEMM_SMEM (A_BYTES + B_BYTES)           // 143360

__global__ void __launch_bounds__(256, 1)
vocab_gemm_kernel() {
    extern __shared__ __align__(16) char smem[];
    __nv_bfloat16* sA = (__nv_bfloat16*)smem;
    __nv_bfloat16* sB = (__nv_bfloat16*)(smem + A_BYTES);

    const int tid = threadIdx.x;
    const int wid = tid >> 5;
    const int v0  = blockIdx.x * BM;            // vocab row base
    const int n0  = blockIdx.y * BN;            // output col base
    const int wm  = wid >> 1, wn = wid & 1;     // warp tile: 32 rows x 64 cols

    // stage A (contiguous vocab rows) and B slice
    #pragma unroll 4
    for (int idx = tid; idx < BM * 32; idx += 256) {
        int r = idx >> 5, c = idx & 31;
        ((uint4*)(sA + r * LDA))[c] =
            *((const uint4*)(g_emb16 + (size_t)(v0 + r) * XDIM) + c);
    }
    #pragma unroll 4
    for (int idx = tid; idx < XDIM * 16; idx += 256) {
        int r = idx >> 4, c = idx & 15;
        ((uint4*)(sB + r * LDB))[c] = *((const uint4*)(g_Wc + (size_t)r * OUTC + n0) + c);
    }
    __syncthreads();

    wmma::fragment<wmma::accumulator, 16, 16, 16, float> acc[2][4];
    #pragma unroll
    for (int mi = 0; mi < 2; ++mi)
        #pragma unroll
        for (int ni = 0; ni < 4; ++ni)
            wmma::fill_fragment(acc[mi][ni], 0.0f);

    #pragma unroll
    for (int k = 0; k < 16; ++k) {
        const int k0 = k * 16;
        wmma::fragment<wmma::matrix_a, 16, 16, 16, __nv_bfloat16, wmma::row_major> af[2];
        wmma::fragment<wmma::matrix_b, 16, 16, 16, __nv_bfloat16, wmma::row_major> bf_[4];
        #pragma unroll
        for (int mi = 0; mi < 2; ++mi)
            wmma::load_matrix_sync(af[mi], sA + (wm * 32 + mi * 16) * LDA + k0, LDA);
        #pragma unroll
        for (int ni = 0; ni < 4; ++ni)
            wmma::load_matrix_sync(bf_[ni], sB + k0 * LDB + (wn * 64 + ni * 16), LDB);
        #pragma unroll
        for (int mi = 0; mi < 2; ++mi)
            #pragma unroll
            for (int ni = 0; ni < 4; ++ni)
                wmma::mma_sync(acc[mi][ni], af[mi], bf_[ni], acc[mi][ni]);
    }

    // direct store (VOCAB % 128 == 0 -> always full tiles)
    #pragma unroll
    for (int mi = 0; mi < 2; ++mi)
        #pragma unroll
        for (int ni = 0; ni < 4; ++ni)
            wmma::store_matrix_sync(
                g_Wemb + (size_t)(v0 + wm * 32 + mi * 16) * OUTC + n0 + wn * 64 + ni * 16,
                acc[mi][ni], OUTC, wmma::mem_row_major);
}

// ---------------- fin: gather-from-Wemb aggregation + relu/select + gate ----------------
// warp per node. For parent p: h = relu(b + Wemb_t[type[p]] + sum_ch (a + alpha_ch * b)(type[ch]))
// For leaf: h = emb[type[p]]. Also computes gate score.
__global__ void fin_kernel(const int* __restrict__ node_type,
                           const int* __restrict__ edge_src,
                           const int* __restrict__ child_count,
                           const float* __restrict__ emb,
                           const float* __restrict__ b_conv,
                           const float* __restrict__ gate_w,
                           const float* __restrict__ gate_b, int N) {
    const int wid = threadIdx.x >> 5, lane = threadIdx.x & 31;
    const int p = blockIdx.x * 8 + wid;
    if (p >= N) return;

    const size_t rowoff = (size_t)p * XDIM;
    const int cc = __ldg(&child_count[p]);
    float4 v0, v1;                               // cols lane*4.. and 128+lane*4..
    if (cc > 0) {
        const int tp = __ldg(&node_type[p]);
        const float* trow = g_Wemb + (size_t)tp * OUTC + 512;
        v0 = *(const float4*)(trow + lane * 4);
        v1 = *(const float4*)(trow + 128 + lane * 4);
        float4 bb0 = *(const float4*)(b_conv + lane * 4);
        float4 bb1 = *(const float4*)(b_conv + 128 + lane * 4);
        v0.x += bb0.x; v0.y += bb0.y; v0.z += bb0.z; v0.w += bb0.w;
        v1.x += bb1.x; v1.y += bb1.y; v1.z += bb1.z; v1.w += bb1.w;
        const int st = __ldg(&g_start[p]);
        for (int k = 0; k < cc; ++k) {
            const int ch = __ldg(&edge_src[st + k]);     // uniform in warp
            const int ty = __ldg(&node_type[ch]);
            const float al = __ldg(&g_alpha[ch]);
            const float* ab = g_Wemb + (size_t)ty * OUTC;
            // interleaved (a,b): cols c -> floats 2c, 2c+1
            float4 p0 = *(const float4*)(ab + 8 * lane);           // a0 b0 a1 b1
            float4 q0 = *(const float4*)(ab + 8 * lane + 4);       // a2 b2 a3 b3
            float4 p1 = *(const float4*)(ab + 256 + 8 * lane);
            float4 q1 = *(const float4*)(ab + 256 + 8 * lane + 4);
            v0.x += fmaf(al, p0.y, p0.x);
            v0.y += fmaf(al, p0.w, p0.z);
            v0.z += fmaf(al, q0.y, q0.x);
            v0.w += fmaf(al, q0.w, q0.z);
            v1.x += fmaf(al, p1.y, p1.x);
            v1.y += fmaf(al, p1.w, p1.z);
            v1.z += fmaf(al, q1.y, q1.x);
            v1.w += fmaf(al, q1.w, q1.z);
        }
        v0.x = fmaxf(v0.x, 0.f); v0.y = fmaxf(v0.y, 0.f);
        v0.z = fmaxf(v0.z, 0.f); v0.w = fmaxf(v0.w, 0.f);
        v1.x = fmaxf(v1.x, 0.f); v1.y = fmaxf(v1.y, 0.f);
        v1.z = fmaxf(v1.z, 0.f); v1.w = fmaxf(v1.w, 0.f);
    } else {
        const float* e = emb + (size_t)__ldg(&node_type[p]) * XDIM;
        v0 = *(const float4*)(e + lane * 4);
        v1 = *(const float4*)(e + 128 + lane * 4);
    }
    *(float4*)(g_T + rowoff + lane * 4) = v0;
    *(float4*)(g_T + rowoff + 128 + lane * 4) = v1;

    float4 w0 = *(const float4*)(gate_w + lane * 4);
    float4 w1 = *(const float4*)(gate_w + 128 + lane * 4);
    float gc = v0.x * w0.x + v0.y * w0.y + v0.z * w0.z + v0.w * w0.w
             + v1.x * w1.x + v1.y * w1.y + v1.z * w1.z + v1.w * w1.w;
    #pragma unroll
    for (int off = 16; off; off >>= 1) gc += __shfl_down_sync(0xffffffffu, gc, off);
    if (lane == 0) g_gate[p] = gc + __ldg(gate_b);
}

// ---------------- per-graph softmax -> attn ----------------
__global__ void stats_kernel(int per) {
    const int g = blockIdx.x, tid = threadIdx.x;
    const int base = g * per;
    __shared__ float s_red[8];
    __shared__ float s_max, s_sum;

    float m = -1e30f;
    for (int n = tid; n < per; n += 256) m = fmaxf(m, g_gate[base + n]);
    #pragma unroll
    for (int off = 16; off; off >>= 1) m = fmaxf(m, __shfl_down_sync(0xffffffffu, m, off));
    if ((tid & 31) == 0) s_red[tid >> 5] = m;
    __syncthreads();
    if (tid == 0) {
        float mm = s_red[0];
        #pragma unroll
        for (int w = 1; w < 8; ++w) mm = fmaxf(mm, s_red[w]);
        s_max = mm;
    }
    __syncthreads();
    const float mm = s_max;

    float s = 0.0f;
    for (int n = tid; n < per; n += 256) s += expf(g_gate[base + n] - mm);
    #pragma unroll
    for (int off = 16; off; off >>= 1) s += __shfl_down_sync(0xffffffffu, s, off);
    if ((tid & 31) == 0) s_red[tid >> 5] = s;
    __syncthreads();
    if (tid == 0) {
        float ss = 0.0f;
        #pragma unroll
        for (int w = 0; w < 8; ++w) ss += s_red[w];
        s_sum = ss;
    }
    __syncthreads();
    const float inv = 1.0f / s_sum;
    for (int n = tid; n < per; n += 256) g_attn[base + n] = expf(g_gate[base + n] - mm) * inv;
}

// ---------------- weighted pooling (deterministic split-4) ----------------
__global__ void pool_kernel(int per) {
    const int g = blockIdx.x, seg = blockIdx.y, tid = threadIdx.x;
    const int chunk = per / SPLIT;
    const int n0 = g * per + seg * chunk;
    const int n1 = (seg == SPLIT - 1) ? (g * per + per) : (n0 + chunk);
    float a0 = 0.f, a1 = 0.f, a2 = 0.f, a3 = 0.f;
    int n = n0;
    for (; n + 4 <= n1; n += 4) {
        a0 = fmaf(__ldg(&g_attn[n + 0]), g_T[(size_t)(n + 0) * XDIM + tid], a0);
        a1 = fmaf(__ldg(&g_attn[n + 1]), g_T[(size_t)(n + 1) * XDIM + tid], a1);
        a2 = fmaf(__ldg(&g_attn[n + 2]), g_T[(size_t)(n + 2) * XDIM + tid], a2);
        a3 = fmaf(__ldg(&g_attn[n + 3]), g_T[(size_t)(n + 3) * XDIM + tid], a3);
    }
    for (; n < n1; ++n) a0 = fmaf(__ldg(&g_attn[n]), g_T[(size_t)n * XDIM + tid], a0);
    g_pooledp[(size_t)(g * SPLIT + seg) * XDIM + tid] = (a0 + a1) + (a2 + a3);
}

// ---------------- classifier ----------------
__global__ void final_kernel(const float* __restrict__ cls_w,
                             const float* __restrict__ cls_b,
                             float* __restrict__ out) {
    const int g = blockIdx.x, tid = threadIdx.x;   // 128 threads
    __shared__ float sp[XDIM];
    for (int c = tid; c < XDIM; c += 128) {
        float s = 0.0f;
        #pragma unroll
        for (int sgm = 0; sgm < SPLIT; ++sgm)
            s += g_pooledp[(size_t)(g * SPLIT + sgm) * XDIM + c];
        sp[c] = s;
    }
    __syncthreads();
    if (tid < NCLS) {
        float acc = cls_b[tid];
        #pragma unroll 8
        for (int c = 0; c < XDIM; ++c)
            acc = fmaf(sp[c], __ldg(&cls_w[c * NCLS + tid]), acc);
        out[g * NCLS + tid] = acc;
    }
}

// ---------------- launch ----------------
extern "C" void kernel_launch(void* const* d_in, const int* in_sizes, int n_in,
                              void* d_out, int out_size) {
    const int*   node_type   = (const int*)d_in[0];
    const int*   edge_src    = (const int*)d_in[1];
    const int*   edge_dst    = (const int*)d_in[2];
    const float* alpha       = (const float*)d_in[3];
    const int*   child_count = (const int*)d_in[4];
    // d_in[5] = graph_ids (nodes contiguous per graph; unused)
    const float* emb         = (const float*)d_in[6];
    const float* W_left      = (const float*)d_in[7];
    const float* W_right     = (const float*)d_in[8];
    const float* W_top       = (const float*)d_in[9];
    const float* b_conv      = (const float*)d_in[10];
    const float* gate_w      = (const float*)d_in[11];
    const float* gate_b      = (const float*)d_in[12];
    const float* cls_w       = (const float*)d_in[13];
    const float* cls_b       = (const float*)d_in[14];
    float* out = (float*)d_out;

    const int N = in_sizes[0];
    const int E = in_sizes[1];
    const int G = out_size / NCLS;
    const int per = N / G;

    cudaFuncSetAttribute(vocab_gemm_kernel, cudaFuncAttributeMaxDynamicSharedMemorySize, GEMM_SMEM);

    {   // prep (3 launches; vocab_gemm lands in the profiled 4th slot)
        int total4 = (VOCAB * XDIM) / 4;
        conv_emb_kernel<<<(total4 + 255) / 256, 256>>>(emb, total4);
        build_wc_kernel<<<(XDIM * OUTC + 255) / 256, 256>>>(W_left, W_right, W_top);
        edge_prep_kernel<<<(E + 255) / 256, 256>>>(edge_src, edge_dst, alpha, E);
    }

    dim3 gg(VOCAB / BM, OUTC / BN);              // 250 x 6
    vocab_gemm_kernel<<<gg, 256, GEMM_SMEM>>>();

    fin_kernel<<<(N + 7) / 8, 256>>>(node_type, edge_src, child_count,
                                     emb, b_conv, gate_w, gate_b, N);

    stats_kernel<<<G, 256>>>(per);

    dim3 pg(G, SPLIT);
    pool_kernel<<<pg, 256>>>(per);

    final_kernel<<<G, 128>>>(cls_w, cls_b, out);
}

// round 7
// speedup vs baseline: 3.7488x; 1.1084x over previous
#include <cuda_runtime.h>
#include <cuda_bf16.h>
#include <mma.h>
#include <math.h>
#include <cstdint>

using namespace nvcuda;

// ---------------- problem constants ----------------
#define NMAXN   409600
#define VOCAB   32000
#define XDIM    256
#define OUTC    768          // 512 interleaved (a,b) + 256 t
#define GMAXG   512
#define NCLS    104
#define SPLIT   4

// ---------------- scratch (device globals; no allocation) ----------------
__device__ __nv_bfloat16 g_emb16[(size_t)VOCAB * XDIM];   // 16 MB
__device__ __nv_bfloat16 g_Wc[(size_t)XDIM * OUTC];       // fused weights, k-major
__device__ __nv_bfloat16 g_Wab[(size_t)VOCAB * 512];      // (a,b) interleaved, bf16 (32 MB)
__device__ float         g_Wt[(size_t)VOCAB * XDIM];      // t = emb@Wt, fp32 (32 MB)
__device__ float g_alpha[NMAXN];
__device__ int   g_start[NMAXN];                          // CSR starts (edges sorted by dst)
__device__ float g_T[(size_t)NMAXN * XDIM];               // h_final (parents only)
__device__ float g_gate[NMAXN];
__device__ float g_attn[NMAXN];
__device__ float g_pooledp[(size_t)GMAXG * SPLIT * XDIM];

// ---------------- prep kernels ----------------
__global__ void conv_emb_kernel(const float* __restrict__ emb, int total4) {
    int i = blockIdx.x * blockDim.x + threadIdx.x;
    if (i < total4) {
        float4 v = ((const float4*)emb)[i];
        ((__nv_bfloat162*)g_emb16)[2 * i]     = __floats2bfloat162_rn(v.x, v.y);
        ((__nv_bfloat162*)g_emb16)[2 * i + 1] = __floats2bfloat162_rn(v.z, v.w);
    }
}

// Wc[k][2j] = Wl[k][j]; Wc[k][2j+1] = Wr[k][j]-Wl[k][j]; Wc[k][512+j] = Wt[k][j]
__global__ void build_wc_kernel(const float* __restrict__ Wl,
                                const float* __restrict__ Wr,
                                const float* __restrict__ Wt) {
    int idx = blockIdx.x * blockDim.x + threadIdx.x;
    if (idx < XDIM * OUTC) {
        int k = idx / OUTC, c = idx % OUTC;
        float v;
        if (c < 2 * XDIM) {
            int j = c >> 1;
            float l = Wl[k * XDIM + j];
            v = (c & 1) ? (Wr[k * XDIM + j] - l) : l;
        } else {
            v = Wt[k * XDIM + (c - 2 * XDIM)];
        }
        g_Wc[idx] = __float2bfloat16(v);
    }
}

// fused: alpha scatter + CSR segment starts (edges sorted by dst)
__global__ void edge_prep_kernel(const int* __restrict__ edge_src,
                                 const int* __restrict__ edge_dst,
                                 const float* __restrict__ alpha, int E) {
    int e = blockIdx.x * blockDim.x + threadIdx.x;
    if (e < E) {
        g_alpha[edge_src[e]] = alpha[e];
        int d = edge_dst[e];
        if (e == 0 || edge_dst[e - 1] != d) g_start[d] = e;
    }
}

// ---------------- vocab GEMM: [32000,256]x[256,768] -> g_Wab (bf16) / g_Wt (fp32) ----------
#define BM 128
#define BN 128
#define LDA 272
#define LDB 144
#define A_BYTES (BM * LDA * 2)                  // 69632
#define B_BYTES (XDIM * LDB * 2)                // 73728
#define GEMM_SMEM (A_BYTES + B_BYTES)           // 143360

__global__ void __launch_bounds__(256, 1)
vocab_gemm_kernel() {
    extern __shared__ __align__(16) char smem[];
    __nv_bfloat16* sA = (__nv_bfloat16*)smem;
    __nv_bfloat16* sB = (__nv_bfloat16*)(smem + A_BYTES);

    const int tid = threadIdx.x;
    const int wid = tid >> 5;
    const int v0  = blockIdx.x * BM;            // vocab row base
    const int y   = blockIdx.y;
    const int n0  = y * BN;                     // output col base (of 768)
    const int wm  = wid >> 1, wn = wid & 1;     // warp tile: 32 rows x 64 cols

    #pragma unroll 4
    for (int idx = tid; idx < BM * 32; idx += 256) {
        int r = idx >> 5, c = idx & 31;
        ((uint4*)(sA + r * LDA))[c] =
            *((const uint4*)(g_emb16 + (size_t)(v0 + r) * XDIM) + c);
    }
    #pragma unroll 4
    for (int idx = tid; idx < XDIM * 16; idx += 256) {
        int r = idx >> 4, c = idx & 15;
        ((uint4*)(sB + r * LDB))[c] = *((const uint4*)(g_Wc + (size_t)r * OUTC + n0) + c);
    }
    __syncthreads();

    wmma::fragment<wmma::accumulator, 16, 16, 16, float> acc[2][4];
    #pragma unroll
    for (int mi = 0; mi < 2; ++mi)
        #pragma unroll
        for (int ni = 0; ni < 4; ++ni)
            wmma::fill_fragment(acc[mi][ni], 0.0f);

    #pragma unroll
    for (int k = 0; k < 16; ++k) {
        const int k0 = k * 16;
        wmma::fragment<wmma::matrix_a, 16, 16, 16, __nv_bfloat16, wmma::row_major> af[2];
        wmma::fragment<wmma::matrix_b, 16, 16, 16, __nv_bfloat16, wmma::row_major> bf_[4];
        #pragma unroll
        for (int mi = 0; mi < 2; ++mi)
            wmma::load_matrix_sync(af[mi], sA + (wm * 32 + mi * 16) * LDA + k0, LDA);
        #pragma unroll
        for (int ni = 0; ni < 4; ++ni)
            wmma::load_matrix_sync(bf_[ni], sB + k0 * LDB + (wn * 64 + ni * 16), LDB);
        #pragma unroll
        for (int mi = 0; mi < 2; ++mi)
            #pragma unroll
            for (int ni = 0; ni < 4; ++ni)
                wmma::mma_sync(acc[mi][ni], af[mi], bf_[ni], acc[mi][ni]);
    }

    if (y >= 4) {
        // t tile: direct fp32 store
        const int cb = (y - 4) * BN;
        #pragma unroll
        for (int mi = 0; mi < 2; ++mi)
            #pragma unroll
            for (int ni = 0; ni < 4; ++ni)
                wmma::store_matrix_sync(
                    g_Wt + (size_t)(v0 + wm * 32 + mi * 16) * XDIM + cb + wn * 64 + ni * 16,
                    acc[mi][ni], XDIM, wmma::mem_row_major);
    } else {
        // ab tile: stage fp32 in smem (reuse sA), convert to bf16
        __syncthreads();
        float* sAcc = (float*)sA;                // 64 KB <= A_BYTES
        #pragma unroll
        for (int mi = 0; mi < 2; ++mi)
            #pragma unroll
            for (int ni = 0; ni < 4; ++ni)
                wmma::store_matrix_sync(sAcc + (wm * 32 + mi * 16) * BN + (wn * 64 + ni * 16),
                                        acc[mi][ni], BN, wmma::mem_row_major);
        __syncthreads();
        #pragma unroll 4
        for (int idx = tid; idx < BM * 64; idx += 256) {   // 128 rows x 64 bf16x2
            int r = idx >> 6, q = idx & 63;
            float2 f = *(const float2*)&sAcc[r * BN + 2 * q];
            *(__nv_bfloat162*)(g_Wab + (size_t)(v0 + r) * 512 + n0 + 2 * q) =
                __floats2bfloat162_rn(f.x, f.y);
        }
    }
}

// ---------------- fin: gather aggregation + relu + gate (warp per node) ----------------
// parent: h = relu(b_conv + Wt[type[p]] + sum_ch (a + alpha_ch*b)[type[ch]]); write g_T.
// leaf:   h = emb[type[p]] (NOT written; pool reads emb directly). Gate computed for all.
__global__ void fin_kernel(const int* __restrict__ node_type,
                           const int* __restrict__ edge_src,
                           const int* __restrict__ child_count,
                           const float* __restrict__ emb,
                           const float* __restrict__ b_conv,
                           const float* __restrict__ gate_w,
                           const float* __restrict__ gate_b, int N) {
    const int wid = threadIdx.x >> 5, lane = threadIdx.x & 31;
    const int p = blockIdx.x * 8 + wid;
    if (p >= N) return;

    const int cc = __ldg(&child_count[p]);
    float4 v0, v1;                               // cols lane*4.., 128+lane*4..
    if (cc > 0) {
        const int tp = __ldg(&node_type[p]);
        const float* trow = g_Wt + (size_t)tp * XDIM;
        v0 = *(const float4*)(trow + lane * 4);
        v1 = *(const float4*)(trow + 128 + lane * 4);
        float4 bb0 = *(const float4*)(b_conv + lane * 4);
        float4 bb1 = *(const float4*)(b_conv + 128 + lane * 4);
        v0.x += bb0.x; v0.y += bb0.y; v0.z += bb0.z; v0.w += bb0.w;
        v1.x += bb1.x; v1.y += bb1.y; v1.z += bb1.z; v1.w += bb1.w;
        const int st = __ldg(&g_start[p]);
        for (int k = 0; k < cc; ++k) {
            const int ch = __ldg(&edge_src[st + k]);     // uniform in warp
            const int ty = __ldg(&node_type[ch]);
            const float al = __ldg(&g_alpha[ch]);
            const uint4* abp = (const uint4*)(g_Wab + (size_t)ty * 512);
            uint4 u0 = abp[lane];                        // cols 4*lane..+3 (a,b pairs)
            uint4 u1 = abp[32 + lane];                   // cols 128+4*lane..+3
            const __nv_bfloat162* p0 = (const __nv_bfloat162*)&u0;
            const __nv_bfloat162* p1 = (const __nv_bfloat162*)&u1;
            float2 f;
            f = __bfloat1622float2(p0[0]); v0.x += fmaf(al, f.y, f.x);
            f = __bfloat1622float2(p0[1]); v0.y += fmaf(al, f.y, f.x);
            f = __bfloat1622float2(p0[2]); v0.z += fmaf(al, f.y, f.x);
            f = __bfloat1622float2(p0[3]); v0.w += fmaf(al, f.y, f.x);
            f = __bfloat1622float2(p1[0]); v1.x += fmaf(al, f.y, f.x);
            f = __bfloat1622float2(p1[1]); v1.y += fmaf(al, f.y, f.x);
            f = __bfloat1622float2(p1[2]); v1.z += fmaf(al, f.y, f.x);
            f = __bfloat1622float2(p1[3]); v1.w += fmaf(al, f.y, f.x);
        }
        v0.x = fmaxf(v0.x, 0.f); v0.y = fmaxf(v0.y, 0.f);
        v0.z = fmaxf(v0.z, 0.f); v0.w = fmaxf(v0.w, 0.f);
        v1.x = fmaxf(v1.x, 0.f); v1.y = fmaxf(v1.y, 0.f);
        v1.z = fmaxf(v1.z, 0.f); v1.w = fmaxf(v1.w, 0.f);
        const size_t rowoff = (size_t)p * XDIM;
        *(float4*)(g_T + rowoff + lane * 4) = v0;
        *(float4*)(g_T + rowoff + 128 + lane * 4) = v1;
    } else {
        const float* e = emb + (size_t)__ldg(&node_type[p]) * XDIM;
        v0 = *(const float4*)(e + lane * 4);
        v1 = *(const float4*)(e + 128 + lane * 4);
    }

    float4 w0 = *(const float4*)(gate_w + lane * 4);
    float4 w1 = *(const float4*)(gate_w + 128 + lane * 4);
    float gc = v0.x * w0.x + v0.y * w0.y + v0.z * w0.z + v0.w * w0.w
             + v1.x * w1.x + v1.y * w1.y + v1.z * w1.z + v1.w * w1.w;
    #pragma unroll
    for (int off = 16; off; off >>= 1) gc += __shfl_down_sync(0xffffffffu, gc, off);
    if (lane == 0) g_gate[p] = gc + __ldg(gate_b);
}

// ---------------- per-graph softmax -> attn ----------------
__global__ void stats_kernel(int per) {
    const int g = blockIdx.x, tid = threadIdx.x;
    const int base = g * per;
    __shared__ float s_red[8];
    __shared__ float s_max, s_sum;

    float m = -1e30f;
    for (int n = tid; n < per; n += 256) m = fmaxf(m, g_gate[base + n]);
    #pragma unroll
    for (int off = 16; off; off >>= 1) m = fmaxf(m, __shfl_down_sync(0xffffffffu, m, off));
    if ((tid & 31) == 0) s_red[tid >> 5] = m;
    __syncthreads();
    if (tid == 0) {
        float mm = s_red[0];
        #pragma unroll
        for (int w = 1; w < 8; ++w) mm = fmaxf(mm, s_red[w]);
        s_max = mm;
    }
    __syncthreads();
    const float mm = s_max;

    float s = 0.0f;
    for (int n = tid; n < per; n += 256) s += expf(g_gate[base + n] - mm);
    #pragma unroll
    for (int off = 16; off; off >>= 1) s += __shfl_down_sync(0xffffffffu, s, off);
    if ((tid & 31) == 0) s_red[tid >> 5] = s;
    __syncthreads();
    if (tid == 0) {
        float ss = 0.0f;
        #pragma unroll
        for (int w = 0; w < 8; ++w) ss += s_red[w];
        s_sum = ss;
    }
    __syncthreads();
    const float inv = 1.0f / s_sum;
    for (int n = tid; n < per; n += 256) g_attn[base + n] = expf(g_gate[base + n] - mm) * inv;
}

// ---------------- weighted pooling (split-4; leaf rows read from emb) ----------------
__global__ void pool_kernel(const int* __restrict__ child_count,
                            const int* __restrict__ node_type,
                            const float* __restrict__ emb, int per) {
    const int g = blockIdx.x, seg = blockIdx.y, tid = threadIdx.x;
    const int chunk = per / SPLIT;
    const int n0 = g * per + seg * chunk;
    const int n1 = (seg == SPLIT - 1) ? (g * per + per) : (n0 + chunk);
    float a0 = 0.f, a1 = 0.f;
    int n = n0;
    for (; n + 2 <= n1; n += 2) {
        const float* r0 = (__ldg(&child_count[n]) > 0)
                            ? (g_T + (size_t)n * XDIM)
                            : (emb + (size_t)__ldg(&node_type[n]) * XDIM);
        const float* r1 = (__ldg(&child_count[n + 1]) > 0)
                            ? (g_T + (size_t)(n + 1) * XDIM)
                            : (emb + (size_t)__ldg(&node_type[n + 1]) * XDIM);
        a0 = fmaf(__ldg(&g_attn[n]),     __ldg(r0 + tid), a0);
        a1 = fmaf(__ldg(&g_attn[n + 1]), __ldg(r1 + tid), a1);
    }
    for (; n < n1; ++n) {
        const float* r = (__ldg(&child_count[n]) > 0)
                            ? (g_T + (size_t)n * XDIM)
                            : (emb + (size_t)__ldg(&node_type[n]) * XDIM);
        a0 = fmaf(__ldg(&g_attn[n]), __ldg(r + tid), a0);
    }
    g_pooledp[(size_t)(g * SPLIT + seg) * XDIM + tid] = a0 + a1;
}

// ---------------- classifier ----------------
__global__ void final_kernel(const float* __restrict__ cls_w,
                             const float* __restrict__ cls_b,
                             float* __restrict__ out) {
    const int g = blockIdx.x, tid = threadIdx.x;   // 128 threads
    __shared__ float sp[XDIM];
    for (int c = tid; c < XDIM; c += 128) {
        float s = 0.0f;
        #pragma unroll
        for (int sgm = 0; sgm < SPLIT; ++sgm)
            s += g_pooledp[(size_t)(g * SPLIT + sgm) * XDIM + c];
        sp[c] = s;
    }
    __syncthreads();
    if (tid < NCLS) {
        float acc = cls_b[tid];
        #pragma unroll 8
        for (int c = 0; c < XDIM; ++c)
            acc = fmaf(sp[c], __ldg(&cls_w[c * NCLS + tid]), acc);
        out[g * NCLS + tid] = acc;
    }
}

// ---------------- launch ----------------
extern "C" void kernel_launch(void* const* d_in, const int* in_sizes, int n_in,
                              void* d_out, int out_size) {
    const int*   node_type   = (const int*)d_in[0];
    const int*   edge_src    = (const int*)d_in[1];
    const int*   edge_dst    = (const int*)d_in[2];
    const float* alpha       = (const float*)d_in[3];
    const int*   child_count = (const int*)d_in[4];
    // d_in[5] = graph_ids (nodes contiguous per graph; unused)
    const float* emb         = (const float*)d_in[6];
    const float* W_left      = (const float*)d_in[7];
    const float* W_right     = (const float*)d_in[8];
    const float* W_top       = (const float*)d_in[9];
    const float* b_conv      = (const float*)d_in[10];
    const float* gate_w      = (const float*)d_in[11];
    const float* gate_b      = (const float*)d_in[12];
    const float* cls_w       = (const float*)d_in[13];
    const float* cls_b       = (const float*)d_in[14];
    float* out = (float*)d_out;

    const int N = in_sizes[0];
    const int E = in_sizes[1];
    const int G = out_size / NCLS;
    const int per = N / G;

    cudaFuncSetAttribute(vocab_gemm_kernel, cudaFuncAttributeMaxDynamicSharedMemorySize, GEMM_SMEM);

    {   // prep (3 launches; vocab_gemm lands in the profiled 4th slot)
        int total4 = (VOCAB * XDIM) / 4;
        conv_emb_kernel<<<(total4 + 255) / 256, 256>>>(emb, total4);
        build_wc_kernel<<<(XDIM * OUTC + 255) / 256, 256>>>(W_left, W_right, W_top);
        edge_prep_kernel<<<(E + 255) / 256, 256>>>(edge_src, edge_dst, alpha, E);
    }

    dim3 gg(VOCAB / BM, OUTC / BN);              // 250 x 6
    vocab_gemm_kernel<<<gg, 256, GEMM_SMEM>>>();

    fin_kernel<<<(N + 7) / 8, 256>>>(node_type, edge_src, child_count,
                                     emb, b_conv, gate_w, gate_b, N);

    stats_kernel<<<G, 256>>>(per);

    dim3 pg(G, SPLIT);
    pool_kernel<<<pg, 256>>>(child_count, node_type, emb, per);

    final_kernel<<<G, 128>>>(cls_w, cls_b, out);
}